// round 13
// baseline (speedup 1.0000x reference)
#include <cuda_runtime.h>
#include <cstdint>

#define HIN 512
#define WIN 512
#define NP  724
#define NA  180
#define PAD 106
#define CENTER 361.5f
#define BOFF 255.5f          // CENTER - PAD: output->image pixel space
#define PI_D 3.14159265358979323846
#define TILE 32
#define NT   23              // ceil(724/32)
#define TDIM 48              // smem tile i-extent (samples span <= 46)
#define TSTR 49              // j-stride (odd -> conflict-free fills)

__global__ void zero_sino_kernel(float* __restrict__ sino) {
    const int i = blockIdx.x * 256 + threadIdx.x;
    if (i < NA * NP) sino[i] = 0.f;
}

// Block: one 32x32 output tile of one angle. Stage the image footprint in smem,
// then bilinear-gather with LDS (bank-granular) instead of LDG (line-granular).
template <bool STEEP>
__global__ __launch_bounds__(256) void radon_kernel(
    const float* __restrict__ img,   // [512,512]
    float* __restrict__ sino,        // [180,724]  (pre-zeroed, atomicAdd)
    float* __restrict__ rot)         // [180,724,724]
{
    __shared__ float tile[TDIM * TSTR];

    const int X0 = blockIdx.x * TILE;
    const int Y0 = blockIdx.y * TILE;
    const int n  = STEEP ? (int)blockIdx.z + 45
                         : ((int)blockIdx.z < 45 ? (int)blockIdx.z : (int)blockIdx.z + 90);
    const int t  = threadIdx.x;
    const int tx = t & 31;
    const int ty = t >> 5;           // 0..7

    float s, c;
    sincosf((float)n * (float)(PI_D / 179.0), &s, &c);

    // image-space coords: ix = c*u - s*v + BOFF ; iy = s*u + c*v + BOFF
    const float u0 = (float)X0 - CENTER, u1 = u0 + 31.0f;
    const float v0 = (float)Y0 - CENTER, v1 = v0 + 31.0f;
    const float ixmin = BOFF + fminf(fminf(c * u0 - s * v0, c * u1 - s * v0),
                                     fminf(c * u0 - s * v1, c * u1 - s * v1));
    const float iymin = BOFF + fminf(fminf(s * u0 + c * v0, s * u1 + c * v0),
                                     fminf(s * u0 + c * v1, s * u1 + c * v1));
    // i = warp-compact image dim (col if shallow, row if steep); j = the other
    const int imin = (int)floorf(STEEP ? iymin : ixmin);
    const int jmin = (int)floorf(STEEP ? ixmin : iymin);

    // does the tile's 2x2-extended footprint touch the image at all?
    const bool active = (imin < HIN) && (imin > -(TDIM - 1)) &&
                        (jmin < HIN) && (jmin > -(TDIM - 1));

    float r[4] = {0.f, 0.f, 0.f, 0.f};

    if (active) {
        // fill smem tile: tile[li*TSTR+lj] = a(jmin+lj, imin+li), zero outside img
        //   shallow: a(j,i) = img[j][i]  -> inner loop dim = li (img col)
        //   steep:   a(j,i) = img[i][j]  -> inner loop dim = lj (img col)
#pragma unroll
        for (int q = 0; q < 9; q++) {            // 48*48/256 = 9
            const int idx   = t + q * 256;
            const int inner = idx % TDIM;
            const int outer = idx / TDIM;
            const int li = STEEP ? outer : inner;
            const int lj = STEEP ? inner : outer;
            const int row = STEEP ? imin + li : jmin + lj;
            const int col = STEEP ? jmin + lj : imin + li;
            float val = 0.f;
            if (((unsigned)row < (unsigned)HIN) && ((unsigned)col < (unsigned)WIN))
                val = img[row * WIN + col];
            tile[li * TSTR + lj] = val;
        }
        __syncthreads();

        const float x  = (float)(X0 + tx) - CENTER;
        float yv       = (float)(Y0 + ty) - CENTER;
        float ix = fmaf(c, x, fmaf(-s, yv, BOFF));
        float iy = fmaf(s, x, fmaf( c, yv, BOFF));
        const float dix = -8.0f * s;
        const float diy =  8.0f * c;

#pragma unroll
        for (int k = 0; k < 4; k++) {
            const float fx = floorf(ix);
            const float fy = floorf(iy);
            const float wx = ix - fx;
            const float wy = iy - fy;
            const int cx = (int)fx;
            const int cy = (int)fy;
            const int li = (STEEP ? cy : cx) - imin;
            const int lj = (STEEP ? cx : cy) - jmin;
            const float wi = STEEP ? wy : wx;
            const float wj = STEEP ? wx : wy;

            const int a = li * TSTR + lj;
            const float A = tile[a];             // a(j,   i)
            const float Bv= tile[a + TSTR];      // a(j,   i+1)
            const float C = tile[a + 1];         // a(j+1, i)
            const float D = tile[a + TSTR + 1];  // a(j+1, i+1)

            const float top = fmaf(wi, Bv - A, A);
            const float bot = fmaf(wi, D - C, C);
            r[k] = fmaf(wj, bot - top, top);
            ix += dix;
            iy += diy;
        }
    }

    // write rotated output + reduce row sums into sinogram
    const int xg = X0 + tx;
    const bool xok = (xg < NP);
#pragma unroll
    for (int k = 0; k < 4; k++) {
        const int yg = Y0 + ty + 8 * k;
        const bool yok = (yg < NP);
        if (xok && yok)
            rot[((size_t)n * NP + yg) * NP + xg] = r[k];
        float sv = xok ? r[k] : 0.f;
#pragma unroll
        for (int o = 16; o > 0; o >>= 1)
            sv += __shfl_down_sync(0xffffffffu, sv, o);
        if (active && tx == 0 && yok)
            atomicAdd(&sino[(size_t)n * NP + yg], sv);
    }
}

extern "C" void kernel_launch(void* const* d_in, const int* in_sizes, int n_in,
                              void* d_out, int out_size) {
    const float* x = (const float*)d_in[0];
    float* sino = (float*)d_out;                 // [180,724]
    float* rot  = sino + (size_t)NA * NP;        // [180,1,724,724]

    zero_sino_kernel<<<(NA * NP + 255) / 256, 256>>>(sino);
    dim3 grid(NT, NT, 90);
    radon_kernel<false><<<grid, 256>>>(x, sino, rot);
    radon_kernel<true ><<<grid, 256>>>(x, sino, rot);
}

// round 14
// speedup vs baseline: 1.2946x; 1.2946x over previous
#include <cuda_runtime.h>
#include <cstdint>

#define HIN 512
#define WIN 512
#define NP  724
#define NA  180
#define CENTER 361.5f
#define BOFF 255.5f          // CENTER - PAD: output-grid -> image pixel space
#define PI_D 3.14159265358979323846
#define TILE 32
#define NT   23              // ceil(724/32)
#define TROWS 48             // smem tile rows (image-row extent; need <= 47)
#define TSTR  52             // smem row stride in floats (13 float4, mult of 4)

__global__ void zero_sino_kernel(float* __restrict__ sino) {
    const int i = blockIdx.x * 256 + threadIdx.x;
    if (i < NA * NP) sino[i] = 0.f;
}

// One block = one 32x32 output tile of one angle. Image-axis-aligned smem tile
// (48 rows x 52 cols) staged with aligned LDG.128; gather is 4 LDS + lerp with
// no per-sample bounds checks (tile is zero-padded at fill time).
__global__ __launch_bounds__(256) void radon_kernel(
    const float* __restrict__ img,   // [512,512]
    float* __restrict__ sino,        // [180,724]  (pre-zeroed, atomicAdd)
    float* __restrict__ rot)         // [180,724,724]
{
    __shared__ __align__(16) float tile[TROWS * TSTR];

    const int X0 = blockIdx.x * TILE;
    const int Y0 = blockIdx.y * TILE;
    const int n  = blockIdx.z;
    const int t  = threadIdx.x;
    const int tx = t & 31;
    const int ty = t >> 5;           // 0..7

    float s, c;
    sincosf((float)n * (float)(PI_D / 179.0), &s, &c);

    // bbox of sample coords over the tile (linear map -> corners suffice)
    const float u0 = (float)X0 - CENTER, u1 = u0 + 31.0f;
    const float v0 = (float)Y0 - CENTER, v1 = v0 + 31.0f;
    const float ixmin = BOFF + fminf(fminf(c * u0 - s * v0, c * u1 - s * v0),
                                     fminf(c * u0 - s * v1, c * u1 - s * v1));
    const float iymin = BOFF + fminf(fminf(s * u0 + c * v0, s * u1 + c * v0),
                                     fminf(s * u0 + c * v1, s * u1 + c * v1));
    const int cmin = (int)floorf(ixmin);         // min image col touched
    const int rmin = (int)floorf(iymin);         // min image row touched
    const int cstart = cmin & ~3;                // 4-aligned col base for LDG.128

    // does the footprint intersect the image at all?
    const bool active = (rmin <= 511) && (rmin >= -46) &&
                        (cmin <= 511) && (cmin >= -46);

    float r[4] = {0.f, 0.f, 0.f, 0.f};

    if (active) {
        // fill: 48 rows x 13 float4 (52 cols), zero outside the image
        const float* imgbase = img + ((long long)rmin * WIN + cstart);
#pragma unroll
        for (int q = 0; q < 3; q++) {
            const int idx  = t + q * 256;        // 768 = 3*256 exactly
            const int row  = idx >> 4;           // 0..47
            const int col4 = idx & 15;           // 0..15, use 0..12
            if (col4 < 13) {
                const int gr = rmin + row;
                const int gc = cstart + (col4 << 2);
                const unsigned ok = ((unsigned)gr < (unsigned)HIN) &
                                    ((unsigned)gc < (unsigned)WIN);
                float4 v = make_float4(0.f, 0.f, 0.f, 0.f);
                const float* p = imgbase + row * WIN + (col4 << 2);
                asm volatile(
                    "{\n\t"
                    ".reg .pred p0;\n\t"
                    "setp.ne.u32 p0, %4, 0;\n\t"
                    "@p0 ld.global.nc.v4.f32 {%0, %1, %2, %3}, [%5];\n\t"
                    "}"
                    : "+f"(v.x), "+f"(v.y), "+f"(v.z), "+f"(v.w)
                    : "r"(ok), "l"(p));
                *reinterpret_cast<float4*>(&tile[row * TSTR + (col4 << 2)]) = v;
            }
        }
    }
    __syncthreads();

    if (active) {
        const float u = (float)(X0 + tx) - CENTER;
        const float v = (float)(Y0 + ty) - CENTER;
        float ix = fmaf(c, u, fmaf(-s, v, BOFF));
        float iy = fmaf(s, u, fmaf( c, v, BOFF));
        const float dix = -8.0f * s;
        const float diy =  8.0f * c;
        const int abase = -(rmin * TSTR) - cstart;

#pragma unroll
        for (int k = 0; k < 4; k++) {
            const float fx = floorf(ix);
            const float fy = floorf(iy);
            const float wx = ix - fx;
            const float wy = iy - fy;
            const int a = (int)fy * TSTR + (int)fx + abase;
            const float A = tile[a];
            const float B = tile[a + 1];
            const float C = tile[a + TSTR];
            const float D = tile[a + TSTR + 1];
            const float top = fmaf(wx, B - A, A);
            const float bot = fmaf(wx, D - C, C);
            r[k] = fmaf(wy, bot - top, top);
            ix += dix;
            iy += diy;
        }
    }

    // write rotated output + reduce row sums into sinogram
    const int xg = X0 + tx;
    const bool xok = (xg < NP);
#pragma unroll
    for (int k = 0; k < 4; k++) {
        const int yg = Y0 + ty + 8 * k;
        const bool yok = (yg < NP);
        if (xok && yok)
            rot[((size_t)n * NP + yg) * NP + xg] = r[k];
        float sv = xok ? r[k] : 0.f;
#pragma unroll
        for (int o = 16; o > 0; o >>= 1)
            sv += __shfl_down_sync(0xffffffffu, sv, o);
        if (active && tx == 0 && yok)
            atomicAdd(&sino[(size_t)n * NP + yg], sv);
    }
}

extern "C" void kernel_launch(void* const* d_in, const int* in_sizes, int n_in,
                              void* d_out, int out_size) {
    const float* x = (const float*)d_in[0];
    float* sino = (float*)d_out;                 // [180,724]
    float* rot  = sino + (size_t)NA * NP;        // [180,1,724,724]

    zero_sino_kernel<<<(NA * NP + 255) / 256, 256>>>(sino);
    dim3 grid(NT, NT, NA);
    radon_kernel<<<grid, 256>>>(x, sino, rot);
}

// round 15
// speedup vs baseline: 1.6845x; 1.3011x over previous
#include <cuda_runtime.h>
#include <cstdint>

#define HIN 512
#define WIN 512
#define NP  724
#define NA  180
#define CENTER 361.5f
#define PI_D 3.14159265358979323846
#define TILE 32
#define NT   23              // ceil(724/32)
#define QSTR 520             // quad-buffer row stride in float4
#define QROWS 514

// Quad buffers: buf[(j+2)*QSTR + (i+2)] = (A, C, B, D) for cell (j,i):
//   A=a(j,i)  C=a(j+1,i)  B=a(j,i+1)  D=a(j+1,i+1)
//   g_qN: a(j,i) = img[j][i]   (shallow: i = image col, j = image row)
//   g_qT: a(j,i) = img[i][j]   (steep:   i = image row, j = image col)
__device__ float4 g_qN[QROWS * QSTR];
__device__ float4 g_qT[QROWS * QSTR];

__global__ void zero_sino_kernel(float* __restrict__ sino) {
    const int i = blockIdx.x * 256 + threadIdx.x;
    if (i < NA * NP) sino[i] = 0.f;
}

__global__ __launch_bounds__(256) void prep_kernel(const float* __restrict__ img) {
    __shared__ float tile[34][36];
    const int bx = blockIdx.x * 32;
    const int by = blockIdx.y * 32;
    for (int idx = threadIdx.x; idx < 34 * 34; idx += 256) {
        const int r = idx / 34, c = idx % 34;
        const int gy = by - 1 + r, gx = bx - 1 + c;
        float v = 0.f;
        if ((unsigned)gy < (unsigned)HIN && (unsigned)gx < (unsigned)WIN)
            v = img[gy * WIN + gx];
        tile[r][c] = v;
    }
    __syncthreads();
    for (int idx = threadIdx.x; idx < 33 * 33; idx += 256) {
        const int r = idx / 33, c = idx % 33;
        g_qN[(size_t)(by + 1 + r) * QSTR + (bx + 1 + c)] =
            make_float4(tile[r][c], tile[r + 1][c], tile[r][c + 1], tile[r + 1][c + 1]);
    }
    for (int idx = threadIdx.x; idx < 33 * 33; idx += 256) {
        const int c = idx / 33, r = idx % 33;
        g_qT[(size_t)(bx + 1 + c) * QSTR + (by + 1 + r)] =
            make_float4(tile[r][c], tile[r][c + 1], tile[r + 1][c], tile[r + 1][c + 1]);
    }
}

// Block = 32x32 output tile of one angle. Warp footprint = 8x x 4y (compact),
// results transposed through smem so global stores are STG.128, 1 line / 8 lanes.
template <bool STEEP>
__global__ __launch_bounds__(256) void radon_kernel(
    float* __restrict__ sino,        // [180,724]  (pre-zeroed, atomicAdd)
    float* __restrict__ rot)         // [180,724,724]
{
    __shared__ __align__(16) float sm[32 * 40];   // stride 40: conflict-free both phases

    const int X0 = blockIdx.x * TILE;
    const int Y0 = blockIdx.y * TILE;
    const int n  = STEEP ? (int)blockIdx.z + 45
                         : ((int)blockIdx.z < 45 ? (int)blockIdx.z : (int)blockIdx.z + 90);
    const int t   = threadIdx.x;
    const int lx  = t & 7;           // 0..7  (output-x lane)
    const int row = t >> 3;          // 0..31 (output-y within tile)

    float s, c;
    sincosf((float)n * (float)(PI_D / 179.0), &s, &c);

    // buffer-space coords (fold -PAD+2 = -104): ib = c*u - s*v + B0 etc.
    const float B0 = CENTER - 104.0f;
    const float v  = (float)(Y0 + row) - CENTER;
    const float u0 = (float)(X0 + lx) - CENTER;
    float ixb = fmaf(c, u0, fmaf(-s, v, B0));
    float iyb = fmaf(s, u0, fmaf( c, v, B0));
    const float dix = 8.0f * c;
    const float diy = 8.0f * s;

    const float4* __restrict__ buf = STEEP ? g_qT : g_qN;

    float sum = 0.0f;

#pragma unroll
    for (int k = 0; k < 4; k++) {
        const float fx = floorf(ixb);
        const float fy = floorf(iyb);
        const float wx = ixb - fx;
        const float wy = iyb - fy;
        const int cx = (int)fx;
        const int cy = (int)fy;

        const int   ci = STEEP ? cy : cx;
        const int   rj = STEEP ? cx : cy;
        const float wi = STEEP ? wy : wx;
        const float wj = STEEP ? wx : wy;

        const unsigned inside =
            ((unsigned)(ci - 1) < 513u) & ((unsigned)(rj - 1) < 513u);

        float4 q = make_float4(0.f, 0.f, 0.f, 0.f);
        const float4* p = buf + (size_t)rj * QSTR + ci;
        asm volatile(
            "{\n\t"
            ".reg .pred p0;\n\t"
            "setp.ne.u32 p0, %4, 0;\n\t"
            "@p0 ld.global.nc.v4.f32 {%0, %1, %2, %3}, [%5];\n\t"
            "}"
            : "+f"(q.x), "+f"(q.y), "+f"(q.z), "+f"(q.w)
            : "r"(inside), "l"(p));

        const float top = fmaf(wi, q.z - q.x, q.x);
        const float bot = fmaf(wi, q.w - q.y, q.y);
        float r = fmaf(wj, bot - top, top);
        // mask columns beyond 723 (last x-tile) out of both store and sum
        if (X0 + lx + 8 * k >= NP) r = 0.f;

        sm[row * 40 + lx + 8 * k] = r;
        sum += r;

        ixb += dix;
        iyb += diy;
    }

    // sinogram: reduce over the 8 lx lanes (consecutive lanes share a row)
#pragma unroll
    for (int o = 4; o > 0; o >>= 1)
        sum += __shfl_down_sync(0xffffffffu, sum, o);
    const int yg = Y0 + row;
    if (lx == 0 && yg < NP)
        atomicAdd(&sino[(size_t)n * NP + yg], sum);

    __syncthreads();

    // transposed store: thread -> (row_r, 4-col chunk), STG.128
    const int row_r = t >> 3;
    const int c4    = (t & 7) << 2;
    const int ygs   = Y0 + row_r;
    if (ygs < NP && X0 + c4 < NP) {
        const float4 val = *reinterpret_cast<const float4*>(&sm[row_r * 40 + c4]);
        *reinterpret_cast<float4*>(&rot[((size_t)n * NP + ygs) * NP + X0 + c4]) = val;
    }
}

extern "C" void kernel_launch(void* const* d_in, const int* in_sizes, int n_in,
                              void* d_out, int out_size) {
    const float* x = (const float*)d_in[0];
    float* sino = (float*)d_out;                 // [180,724]
    float* rot  = sino + (size_t)NA * NP;        // [180,1,724,724]

    zero_sino_kernel<<<(NA * NP + 255) / 256, 256>>>(sino);
    prep_kernel<<<dim3(WIN / 32, HIN / 32), 256>>>(x);
    dim3 grid(NT, NT, 90);
    radon_kernel<false><<<grid, 256>>>(sino, rot);
    radon_kernel<true ><<<grid, 256>>>(sino, rot);
}

// round 16
// speedup vs baseline: 1.9546x; 1.1604x over previous
#include <cuda_runtime.h>
#include <cstdint>

#define HIN 512
#define WIN 512
#define NP  724
#define NA  180
#define CENTER 361.5f
#define PI_D 3.14159265358979323846
#define TILE 32
#define NT   23              // ceil(724/32)
#define QSTR 520             // quad-buffer row stride in float4
#define QROWS 514

// Quad buffers: buf[(j+2)*QSTR + (i+2)] = (A, C, B, D) for cell (j,i):
//   A=a(j,i)  C=a(j+1,i)  B=a(j,i+1)  D=a(j+1,i+1)
//   g_qN: a(j,i) = img[j][i]   (shallow: i = image col, j = image row)
//   g_qT: a(j,i) = img[i][j]   (steep:   i = image row, j = image col)
__device__ float4 g_qN[QROWS * QSTR];
__device__ float4 g_qT[QROWS * QSTR];

__global__ __launch_bounds__(256) void prep_kernel(const float* __restrict__ img,
                                                   float* __restrict__ sino) {
    // fused sinogram zeroing: 256 blocks x 256 threads x 2 covers 130320
    const int gid = ((blockIdx.y * 16 + blockIdx.x) * 256 + threadIdx.x) * 2;
    if (gid < NA * NP)     sino[gid] = 0.f;
    if (gid + 1 < NA * NP) sino[gid + 1] = 0.f;

    __shared__ float tile[34][36];
    const int bx = blockIdx.x * 32;
    const int by = blockIdx.y * 32;
    for (int idx = threadIdx.x; idx < 34 * 34; idx += 256) {
        const int r = idx / 34, c = idx % 34;
        const int gy = by - 1 + r, gx = bx - 1 + c;
        float v = 0.f;
        if ((unsigned)gy < (unsigned)HIN && (unsigned)gx < (unsigned)WIN)
            v = img[gy * WIN + gx];
        tile[r][c] = v;
    }
    __syncthreads();
    for (int idx = threadIdx.x; idx < 33 * 33; idx += 256) {
        const int r = idx / 33, c = idx % 33;
        g_qN[(size_t)(by + 1 + r) * QSTR + (bx + 1 + c)] =
            make_float4(tile[r][c], tile[r + 1][c], tile[r][c + 1], tile[r + 1][c + 1]);
    }
    for (int idx = threadIdx.x; idx < 33 * 33; idx += 256) {
        const int c = idx / 33, r = idx % 33;
        g_qT[(size_t)(bx + 1 + c) * QSTR + (by + 1 + r)] =
            make_float4(tile[r][c], tile[r][c + 1], tile[r + 1][c], tile[r + 1][c + 1]);
    }
}

// Block = 32x32 output tile of one angle; warp footprint 8x x 4y.
// Block-uniform specialization: fully-OOB -> zero-store fast exit;
// fully-interior -> unconditional LDG.128; boundary -> predicated LDG.128.
template <bool STEEP>
__global__ __launch_bounds__(256) void radon_kernel(
    float* __restrict__ sino,        // [180,724]  (pre-zeroed, atomicAdd)
    float* __restrict__ rot)         // [180,724,724]
{
    __shared__ __align__(16) float sm[32 * 40];

    const int X0 = blockIdx.x * TILE;
    const int Y0 = blockIdx.y * TILE;
    const int n  = STEEP ? (int)blockIdx.z + 45
                         : ((int)blockIdx.z < 45 ? (int)blockIdx.z : (int)blockIdx.z + 90);
    const int t   = threadIdx.x;
    const int lx  = t & 7;           // 0..7  (output-x lane)
    const int row = t >> 3;          // 0..31 (output-y within tile)

    float s, c;
    sincosf((float)n * (float)(PI_D / 179.0), &s, &c);

    // tile bbox in buffer space (linear map -> corners suffice)
    const float B0 = CENTER - 104.0f;    // folds -PAD+2
    const float u0 = (float)X0 - CENTER, u1 = u0 + 31.0f;
    const float v0 = (float)Y0 - CENTER, v1 = v0 + 31.0f;
    const float e00x = c * u0 - s * v0, e10x = c * u1 - s * v0;
    const float e01x = c * u0 - s * v1, e11x = c * u1 - s * v1;
    const float e00y = s * u0 + c * v0, e10y = s * u1 + c * v0;
    const float e01y = s * u0 + c * v1, e11y = s * u1 + c * v1;
    const float ixmin = B0 + fminf(fminf(e00x, e10x), fminf(e01x, e11x));
    const float ixmax = B0 + fmaxf(fmaxf(e00x, e10x), fmaxf(e01x, e11x));
    const float iymin = B0 + fminf(fminf(e00y, e10y), fminf(e01y, e11y));
    const float iymax = B0 + fmaxf(fmaxf(e00y, e10y), fmaxf(e01y, e11y));
    const int cimin = (int)floorf(STEEP ? iymin : ixmin);
    const int cimax = (int)floorf(STEEP ? iymax : ixmax);
    const int rjmin = (int)floorf(STEEP ? ixmin : iymin);
    const int rjmax = (int)floorf(STEEP ? ixmax : iymax);

    const bool active = (cimax >= 1) && (cimin <= 513) &&
                        (rjmax >= 1) && (rjmin <= 513);

    const int row_r = t >> 3;
    const int c4    = (t & 7) << 2;
    const int ygs   = Y0 + row_r;

    if (!active) {
        // whole tile outside the image: rotated block is exactly zero
        if (ygs < NP && X0 + c4 < NP)
            *reinterpret_cast<float4*>(&rot[((size_t)n * NP + ygs) * NP + X0 + c4]) =
                make_float4(0.f, 0.f, 0.f, 0.f);
        return;
    }

    const bool allin = (cimin >= 1) && (cimax <= 513) &&
                       (rjmin >= 1) && (rjmax <= 513);

    const float v  = (float)(Y0 + row) - CENTER;
    const float uu = (float)(X0 + lx) - CENTER;
    float ixb = fmaf(c, uu, fmaf(-s, v, B0));
    float iyb = fmaf(s, uu, fmaf( c, v, B0));
    const float dix = 8.0f * c;
    const float diy = 8.0f * s;

    const float4* __restrict__ buf = STEEP ? g_qT : g_qN;
    const int xg0 = X0 + lx;
    float sum = 0.0f;

    if (allin) {
#pragma unroll
        for (int k = 0; k < 4; k++) {
            const float fx = floorf(ixb);
            const float fy = floorf(iyb);
            const float wx = ixb - fx;
            const float wy = iyb - fy;
            const int   ci = (int)(STEEP ? fy : fx);
            const int   rj = (int)(STEEP ? fx : fy);
            const float wi = STEEP ? wy : wx;
            const float wj = STEEP ? wx : wy;

            const float4 q = __ldg(buf + rj * QSTR + ci);
            const float top = fmaf(wi, q.z - q.x, q.x);
            const float bot = fmaf(wi, q.w - q.y, q.y);
            const float r   = fmaf(wj, bot - top, top);

            sm[row * 40 + lx + 8 * k] = r;
            if (xg0 + 8 * k < NP) sum += r;
            ixb += dix;
            iyb += diy;
        }
    } else {
#pragma unroll
        for (int k = 0; k < 4; k++) {
            const float fx = floorf(ixb);
            const float fy = floorf(iyb);
            const float wx = ixb - fx;
            const float wy = iyb - fy;
            const int   ci = (int)(STEEP ? fy : fx);
            const int   rj = (int)(STEEP ? fx : fy);
            const float wi = STEEP ? wy : wx;
            const float wj = STEEP ? wx : wy;

            const unsigned inside =
                ((unsigned)(ci - 1) < 513u) & ((unsigned)(rj - 1) < 513u);
            float4 q = make_float4(0.f, 0.f, 0.f, 0.f);
            const float4* p = buf + (size_t)rj * QSTR + ci;
            asm volatile(
                "{\n\t"
                ".reg .pred p0;\n\t"
                "setp.ne.u32 p0, %4, 0;\n\t"
                "@p0 ld.global.nc.v4.f32 {%0, %1, %2, %3}, [%5];\n\t"
                "}"
                : "+f"(q.x), "+f"(q.y), "+f"(q.z), "+f"(q.w)
                : "r"(inside), "l"(p));

            const float top = fmaf(wi, q.z - q.x, q.x);
            const float bot = fmaf(wi, q.w - q.y, q.y);
            const float r   = fmaf(wj, bot - top, top);

            sm[row * 40 + lx + 8 * k] = r;
            if (xg0 + 8 * k < NP) sum += r;
            ixb += dix;
            iyb += diy;
        }
    }

    // sinogram: reduce over the 8 lx lanes (consecutive lanes share a row)
#pragma unroll
    for (int o = 4; o > 0; o >>= 1)
        sum += __shfl_down_sync(0xffffffffu, sum, o);
    const int yg = Y0 + row;
    if (lx == 0 && yg < NP)
        atomicAdd(&sino[(size_t)n * NP + yg], sum);

    __syncthreads();

    // transposed store: STG.128, one line per 8 lanes
    if (ygs < NP && X0 + c4 < NP) {
        const float4 val = *reinterpret_cast<const float4*>(&sm[row_r * 40 + c4]);
        *reinterpret_cast<float4*>(&rot[((size_t)n * NP + ygs) * NP + X0 + c4]) = val;
    }
}

extern "C" void kernel_launch(void* const* d_in, const int* in_sizes, int n_in,
                              void* d_out, int out_size) {
    const float* x = (const float*)d_in[0];
    float* sino = (float*)d_out;                 // [180,724]
    float* rot  = sino + (size_t)NA * NP;        // [180,1,724,724]

    prep_kernel<<<dim3(16, 16), 256>>>(x, sino);
    dim3 grid(NT, NT, 90);
    radon_kernel<false><<<grid, 256>>>(sino, rot);
    radon_kernel<true ><<<grid, 256>>>(sino, rot);
}